// round 13
// baseline (speedup 1.0000x reference)
#include <cuda_runtime.h>
#include <math_constants.h>

#define NEMB  8192
#define NTOK  32768             // 8 * 4096
#define NBLK  148
#define NTHR  896               // 28 warps
#define CAP1  512               // tier1 capacity (mean ~142)
#define CAP2  1280              // tier2 capacity (mean ~610)
#define TH1   12.0f             // tier1: n2 >= 12
#define TH0   8.0f              // tier2: 8 <= n2 < 12
#define SQ12G (3.46410162f * 1.000002f)
#define SQ8G  (2.82842712f * 1.000002f)

__device__ float d_part[NBLK];
__device__ int   d_done;        // zero-init; self-resetting

__global__ __launch_bounds__(NTHR, 1)
void vq_main_kernel(const float4* __restrict__ x4,
                    const float4* __restrict__ e4,
                    float* __restrict__ out) {
    __shared__ float4 s_t1[CAP1];  __shared__ int s_i1[CAP1];
    __shared__ float4 s_t2[CAP2];  __shared__ int s_i2[CAP2];
    __shared__ float  wred[NTHR / 32];
    __shared__ int    s_cnt1, s_cnt2, s_last;

    const int t    = threadIdx.x;
    const int lane = t & 31;
    const int wid  = t >> 5;
    const int sub  = lane & 3;
    const int tok  = ((int)blockIdx.x * 28 + wid) * 8 + (lane >> 2);
    const bool act = tok < NTOK;

    float4 xv = act ? x4[tok] : make_float4(0.f, 0.f, 0.f, 0.f);
    const float nx = sqrtf(xv.x*xv.x + xv.y*xv.y + xv.z*xv.z + xv.w*xv.w)
                     * 1.000002f;                     // fp-guarded |x|

    if (t == 0) { s_cnt1 = 0; s_cnt2 = 0; s_last = 0; }
    __syncthreads();

    // ---- Phase 1: ballot-compacted staging into 2 norm tiers ----
    for (int base = 0; base < NEMB; base += 3 * NTHR) {
        int ii[3]; float4 ev[3];
        #pragma unroll
        for (int j = 0; j < 3; j++) {                 // 3 loads in flight
            ii[j] = base + t + j * NTHR;
            if (ii[j] < NEMB) ev[j] = e4[ii[j]];
        }
        #pragma unroll
        for (int j = 0; j < 3; j++) {
            bool valid = ii[j] < NEMB;
            float4 e = ev[j];
            float n2 = valid ? (e.x*e.x + e.y*e.y + e.z*e.z + e.w*e.w) : 0.0f;
            bool c1 = valid && (n2 >= TH1);
            bool c2 = valid && (n2 >= TH0) && (n2 < TH1);
            unsigned m1 = __ballot_sync(0xFFFFFFFFu, c1);
            unsigned m2 = __ballot_sync(0xFFFFFFFFu, c2);
            int b1 = 0, b2 = 0;
            if (lane == 0) {
                if (m1) b1 = atomicAdd(&s_cnt1, __popc(m1));
                if (m2) b2 = atomicAdd(&s_cnt2, __popc(m2));
            }
            b1 = __shfl_sync(0xFFFFFFFFu, b1, 0);
            b2 = __shfl_sync(0xFFFFFFFFu, b2, 0);
            unsigned below = (1u << lane) - 1u;
            if (c1) {
                int p = b1 + __popc(m1 & below);
                if (p < CAP1) { s_t1[p] = e; s_i1[p] = ii[j]; }
            }
            if (c2) {
                int p = b2 + __popc(m2 & below);
                if (p < CAP2) { s_t2[p] = e; s_i2[p] = ii[j]; }
            }
        }
    }
    __syncthreads();
    const int  n1   = s_cnt1 < CAP1 ? s_cnt1 : CAP1;
    const int  n2c  = s_cnt2 < CAP2 ? s_cnt2 : CAP2;
    const bool over = (s_cnt1 > CAP1) || (s_cnt2 > CAP2);  // ~never

    // ---- Phase 2a: tier1 scan (no stop machinery) ----
    float best = act ? -CUDART_INF_F : CUDART_INF_F;
    int bidx = NEMB;

    for (int p = 0; p < n1; p += 32) {
        float d[8];
        #pragma unroll
        for (int i = 0; i < 8; i++) {
            int slot = p + sub + 4 * i;               // 4 words/warp: broadcast
            float4 e = s_t1[slot];
            float dd = fmaf(xv.x, e.x, fmaf(xv.y, e.y, fmaf(xv.z, e.z, xv.w * e.w)));
            d[i] = (slot < n1) ? dd : -CUDART_INF_F;
        }
        float om = fmaxf(fmaxf(fmaxf(d[0], d[1]), fmaxf(d[2], d[3])),
                         fmaxf(fmaxf(d[4], d[5]), fmaxf(d[6], d[7])));
        if (om >= best) {
            #pragma unroll
            for (int i = 0; i < 8; i++) {
                int slot = p + sub + 4 * i;
                int id = (slot < n1) ? s_i1[slot] : NEMB;
                if (d[i] > best || (d[i] == best && id < bidx)) {
                    best = d[i]; bidx = id;
                }
            }
        }
    }

    // certificate 1: all unscanned mass has dot <= sqrt(12)*g*|x| < cb (strict:
    // excludes wins AND ties)
    float cb = best;
    cb = fmaxf(cb, __shfl_xor_sync(0xFFFFFFFFu, cb, 1));
    cb = fmaxf(cb, __shfl_xor_sync(0xFFFFFFFFu, cb, 2));
    bool pass1 = (SQ12G * nx < cb);

    // ---- Phase 2b: tier2 scan, only if some quad in the warp needs it ----
    if (!__all_sync(0xFFFFFFFFu, pass1)) {
        for (int p = 0; p < n2c; p += 32) {
            float d[8];
            #pragma unroll
            for (int i = 0; i < 8; i++) {
                int slot = p + sub + 4 * i;
                float4 e = s_t2[slot];
                float dd = fmaf(xv.x, e.x, fmaf(xv.y, e.y, fmaf(xv.z, e.z, xv.w * e.w)));
                d[i] = (slot < n2c) ? dd : -CUDART_INF_F;
            }
            float om = fmaxf(fmaxf(fmaxf(d[0], d[1]), fmaxf(d[2], d[3])),
                             fmaxf(fmaxf(d[4], d[5]), fmaxf(d[6], d[7])));
            if (om >= best) {
                #pragma unroll
                for (int i = 0; i < 8; i++) {
                    int slot = p + sub + 4 * i;
                    int id = (slot < n2c) ? s_i2[slot] : NEMB;
                    if (d[i] > best || (d[i] == best && id < bidx)) {
                        best = d[i]; bidx = id;
                    }
                }
            }
        }
        cb = best;
        cb = fmaxf(cb, __shfl_xor_sync(0xFFFFFFFFu, cb, 1));
        cb = fmaxf(cb, __shfl_xor_sync(0xFFFFFFFFu, cb, 2));
    }

    // final certificate over the n2 < 8 remainder; ~never false for real data
    bool needFB = over ? act : !(SQ8G * nx < cb);

    // exact warp-cooperative full-table fallback (correctness backstop)
    unsigned m = __ballot_sync(0xFFFFFFFFu, needFB);
    while (m) {
        int l = __ffs(m) - 1; int q = l >> 2;
        m &= ~(0xFu << (q << 2));
        int ol = q << 2;
        float tx = __shfl_sync(0xFFFFFFFFu, xv.x, ol);
        float ty = __shfl_sync(0xFFFFFFFFu, xv.y, ol);
        float tz = __shfl_sync(0xFFFFFFFFu, xv.z, ol);
        float tw = __shfl_sync(0xFFFFFFFFu, xv.w, ol);
        float lb = -CUDART_INF_F;
        int lid = NEMB;
        for (int pp = 0; pp < NEMB; pp += 256) {
            #pragma unroll
            for (int i = 0; i < 8; i++) {
                int slot = pp + lane + (i << 5);
                float4 e = e4[slot];
                float dd = fmaf(tx, e.x, fmaf(ty, e.y, fmaf(tz, e.z, tw * e.w)));
                if (dd > lb || (dd == lb && slot < lid)) { lb = dd; lid = slot; }
            }
        }
        #pragma unroll
        for (int o = 16; o; o >>= 1) {
            float vo = __shfl_xor_sync(0xFFFFFFFFu, lb, o);
            int   io = __shfl_xor_sync(0xFFFFFFFFu, lid, o);
            if (vo > lb || (vo == lb && io < lid)) { lb = vo; lid = io; }
        }
        if ((lane >> 2) == q) {
            if (lb > best || (lb == best && lid < bidx)) { best = lb; bidx = lid; }
        }
    }

    // merge quad lanes: max value, ties -> lowest original index
    #pragma unroll
    for (int o = 1; o <= 2; o <<= 1) {
        float vo = __shfl_xor_sync(0xFFFFFFFFu, best, o);
        int   io = __shfl_xor_sync(0xFFFFFFFFu, bidx, o);
        if (vo > best || (vo == best && io < bidx)) { best = vo; bidx = io; }
    }

    float lsum = 0.0f;
    if (act && sub == 0) {
        float4 e = e4[bidx];
        lsum = fabsf(xv.x - e.x) + fabsf(xv.y - e.y)
             + fabsf(xv.z - e.z) + fabsf(xv.w - e.w);
    }

    // reduce: warp -> block
    #pragma unroll
    for (int o = 16; o; o >>= 1)
        lsum += __shfl_down_sync(0xFFFFFFFFu, lsum, o);
    if (lane == 0) wred[wid] = lsum;
    __syncthreads();

    // block partial -> d_part; last-arriving block finalizes
    if (t == 0) {
        float s = 0.0f;
        #pragma unroll
        for (int i = 0; i < NTHR / 32; i++) s += wred[i];
        d_part[blockIdx.x] = s;
        __threadfence();
        if (atomicAdd(&d_done, 1) == NBLK - 1) s_last = 1;
    }
    __syncthreads();
    if (s_last && wid == 0) {
        float s = 0.0f;
        for (int i = lane; i < NBLK; i += 32) s += d_part[i];
        #pragma unroll
        for (int o = 16; o; o >>= 1)
            s += __shfl_down_sync(0xFFFFFFFFu, s, o);
        if (lane == 0) {
            out[0] = s * (2.0f / (float)(NTOK * 4));  // both L1 terms equal
            d_done = 0;                               // reset for graph replay
        }
    }
}

extern "C" void kernel_launch(void* const* d_in, const int* in_sizes, int n_in,
                              void* d_out, int out_size) {
    const float4* x   = (const float4*)d_in[0];   // [8,4096,4] f32
    const float4* emb = (const float4*)d_in[1];   // [8192,4] f32
    float* out = (float*)d_out;

    vq_main_kernel<<<NBLK, NTHR>>>(x, emb, out);
}

// round 14
// speedup vs baseline: 1.3674x; 1.3674x over previous
#include <cuda_runtime.h>
#include <math_constants.h>

#define NEMB  8192
#define NTOK  32768             // 8 * 4096
#define NBLK  148
#define NTHR  896               // 28 warps
#define CAP   1024              // staged capacity (mean ~750)
#define THETA 8.0f              // ||e||^2 cutoff
#define NB2   64
#define WID2  0.5625f           // bin width over n2 in [8, 44)
#define IW2   (1.0f / 0.5625f)
#define SQ8G  (2.82842712f * 1.000002f)   // guarded sqrt(THETA)

__device__ float4 d_stage[CAP];
__device__ int    d_sid[CAP];
__device__ int    d_cnt;        // zero-init; reset by finalizer each call
__device__ float  d_part[NBLK];
__device__ int    d_done;       // zero-init; reset by finalizer each call

// ---- Kernel A: one global pass stages candidates (ballot-compacted) ----
__global__ void vq_stage_kernel(const float4* __restrict__ e4) {
    int i = blockIdx.x * 256 + threadIdx.x;
    float4 e = e4[i];
    float n2 = e.x*e.x + e.y*e.y + e.z*e.z + e.w*e.w;
    bool c = (n2 >= THETA);
    unsigned m = __ballot_sync(0xFFFFFFFFu, c);
    int base = 0;
    if ((threadIdx.x & 31) == 0 && m) base = atomicAdd(&d_cnt, __popc(m));
    base = __shfl_sync(0xFFFFFFFFu, base, 0);
    if (c) {
        int pos = base + __popc(m & ((1u << (threadIdx.x & 31)) - 1u));
        if (pos < CAP) { d_stage[pos] = e; d_sid[pos] = i; }
    }
}

// ---- Kernel B: sort ~750 in smem, pruned scan (R12-validated), loss ----
__global__ __launch_bounds__(NTHR, 1)
void vq_main_kernel(const float4* __restrict__ x4,
                    const float4* __restrict__ e4,
                    float* __restrict__ out) {
    __shared__ float4 s_tbl[CAP];
    __shared__ int    s_sidx[CAP];
    __shared__ int    s_hist[NB2], s_soff[NB2], s_scur[NB2];
    __shared__ float  s_ubs[CAP / 32 + 1];
    __shared__ float  wred[NTHR / 32];
    __shared__ int    s_last;

    const int t    = threadIdx.x;
    const int lane = t & 31;
    const int wid  = t >> 5;
    const int sub  = lane & 3;
    const int tok  = ((int)blockIdx.x * 28 + wid) * 8 + (lane >> 2);
    const bool act = tok < NTOK;

    float4 xv = act ? x4[tok] : make_float4(0.f, 0.f, 0.f, 0.f);
    const float nx = sqrtf(xv.x*xv.x + xv.y*xv.y + xv.z*xv.z + xv.w*xv.w)
                     * 1.000002f;                     // fp-guarded |x|

    if (t < NB2) { s_hist[t] = 0; s_scur[t] = 0; }
    if (t == 0) s_last = 0;
    __syncthreads();

    const int  cnt_all = d_cnt;
    const bool over    = cnt_all > CAP;               // ~never: exact fallback
    const int  cnt     = cnt_all < CAP ? cnt_all : CAP;

    // load staged candidates (<=2 rounds), histogram their bins
    float4 myE[2]; int myI[2], myB[2];
    #pragma unroll
    for (int r = 0; r < 2; r++) {
        int i = t + r * NTHR;
        myB[r] = -1;
        if (i < cnt) {
            float4 e = d_stage[i];
            myE[r] = e; myI[r] = d_sid[i];
            float n2 = e.x*e.x + e.y*e.y + e.z*e.z + e.w*e.w;
            int raw = (int)((n2 - THETA) * IW2);
            raw = raw < 0 ? 0 : (raw > NB2 - 1 ? NB2 - 1 : raw);
            myB[r] = (NB2 - 1) - raw;
            atomicAdd(&s_hist[myB[r]], 1);
        }
    }
    __syncthreads();

    // exclusive prefix over 64 bins (warp 0)
    if (wid == 0) {
        int a = s_hist[lane], b = s_hist[lane + 32];
        int va = a, vb = b;
        #pragma unroll
        for (int o = 1; o < 32; o <<= 1) {
            int u = __shfl_up_sync(0xFFFFFFFFu, va, o); if (lane >= o) va += u;
            int w = __shfl_up_sync(0xFFFFFFFFu, vb, o); if (lane >= o) vb += w;
        }
        int tot = __shfl_sync(0xFFFFFFFFu, va, 31);
        s_soff[lane]      = va - a;
        s_soff[lane + 32] = tot + vb - b;
    }
    __syncthreads();

    // scatter into bin-sorted order + superstep ub
    #pragma unroll
    for (int r = 0; r < 2; r++) {
        if (myB[r] >= 0) {
            int b = myB[r];
            int pos = s_soff[b] + atomicAdd(&s_scur[b], 1);
            s_tbl[pos]  = myE[r];
            s_sidx[pos] = myI[r];
            if ((pos & 31) == 0)        // ub for all slots >= pos
                s_ubs[pos >> 5] = (b == 0) ? CUDART_INF_F
                    : sqrtf(THETA + (float)(NB2 - b) * WID2) * 1.000002f;
        }
    }
    __syncthreads();

    // ---- pruned scan over <=cnt candidates, 4 lanes/token ----
    float best = act ? -CUDART_INF_F : CUDART_INF_F;
    int bidx = NEMB;
    const int nsl = (cnt + 31) & ~31;

    for (int p = 0; p < nsl; p += 32) {
        float ubn = (p + 32 >= cnt) ? SQ8G : s_ubs[(p >> 5) + 1];
        float d[8];
        #pragma unroll
        for (int i = 0; i < 8; i++) {
            int slot = p + sub + 4 * i;               // 4 words/warp: broadcast
            float4 e = s_tbl[slot];
            float dd = fmaf(xv.x, e.x, fmaf(xv.y, e.y, fmaf(xv.z, e.z, xv.w * e.w)));
            d[i] = (slot < cnt) ? dd : -CUDART_INF_F;
        }
        float om = fmaxf(fmaxf(fmaxf(d[0], d[1]), fmaxf(d[2], d[3])),
                         fmaxf(fmaxf(d[4], d[5]), fmaxf(d[6], d[7])));
        if (om >= best) {
            #pragma unroll
            for (int i = 0; i < 8; i++) {
                int slot = p + sub + 4 * i;
                int id = (slot < cnt) ? s_sidx[slot] : NEMB;
                if (d[i] > best || (d[i] == best && id < bidx)) {
                    best = d[i]; bidx = id;
                }
            }
        }
        float cb = best;                 // quad-combined best value
        cb = fmaxf(cb, __shfl_xor_sync(0xFFFFFFFFu, cb, 1));
        cb = fmaxf(cb, __shfl_xor_sync(0xFFFFFFFFu, cb, 2));
        // remaining tier slots <= ubn; sub-theta mass <= SQ8G <= ubn
        if (!over && __all_sync(0xFFFFFFFFu, ubn * nx < cb)) break;
    }

    // final certificate; ~never false for real data
    float cbf = best;
    cbf = fmaxf(cbf, __shfl_xor_sync(0xFFFFFFFFu, cbf, 1));
    cbf = fmaxf(cbf, __shfl_xor_sync(0xFFFFFFFFu, cbf, 2));
    bool needFB = over ? act : !(SQ8G * nx < cbf);

    // exact warp-cooperative full-table fallback (correctness backstop)
    unsigned m = __ballot_sync(0xFFFFFFFFu, needFB);
    while (m) {
        int l = __ffs(m) - 1; int q = l >> 2;
        m &= ~(0xFu << (q << 2));
        int ol = q << 2;
        float tx = __shfl_sync(0xFFFFFFFFu, xv.x, ol);
        float ty = __shfl_sync(0xFFFFFFFFu, xv.y, ol);
        float tz = __shfl_sync(0xFFFFFFFFu, xv.z, ol);
        float tw = __shfl_sync(0xFFFFFFFFu, xv.w, ol);
        float lb = -CUDART_INF_F;
        int lid = NEMB;
        for (int pp = 0; pp < NEMB; pp += 256) {
            #pragma unroll
            for (int i = 0; i < 8; i++) {
                int slot = pp + lane + (i << 5);
                float4 e = e4[slot];
                float dd = fmaf(tx, e.x, fmaf(ty, e.y, fmaf(tz, e.z, tw * e.w)));
                if (dd > lb || (dd == lb && slot < lid)) { lb = dd; lid = slot; }
            }
        }
        #pragma unroll
        for (int o = 16; o; o >>= 1) {
            float vo = __shfl_xor_sync(0xFFFFFFFFu, lb, o);
            int   io = __shfl_xor_sync(0xFFFFFFFFu, lid, o);
            if (vo > lb || (vo == lb && io < lid)) { lb = vo; lid = io; }
        }
        if ((lane >> 2) == q) {
            if (lb > best || (lb == best && lid < bidx)) { best = lb; bidx = lid; }
        }
    }

    // merge quad lanes: max value, ties -> lowest original index
    #pragma unroll
    for (int o = 1; o <= 2; o <<= 1) {
        float vo = __shfl_xor_sync(0xFFFFFFFFu, best, o);
        int   io = __shfl_xor_sync(0xFFFFFFFFu, bidx, o);
        if (vo > best || (vo == best && io < bidx)) { best = vo; bidx = io; }
    }

    float lsum = 0.0f;
    if (act && sub == 0) {
        float4 e = e4[bidx];
        lsum = fabsf(xv.x - e.x) + fabsf(xv.y - e.y)
             + fabsf(xv.z - e.z) + fabsf(xv.w - e.w);
    }

    // reduce: warp -> block
    #pragma unroll
    for (int o = 16; o; o >>= 1)
        lsum += __shfl_down_sync(0xFFFFFFFFu, lsum, o);
    if (lane == 0) wred[wid] = lsum;
    __syncthreads();

    // block partial -> d_part; last-arriving block finalizes + resets state
    if (t == 0) {
        float s = 0.0f;
        #pragma unroll
        for (int i = 0; i < NTHR / 32; i++) s += wred[i];
        d_part[blockIdx.x] = s;
        __threadfence();
        if (atomicAdd(&d_done, 1) == NBLK - 1) s_last = 1;
    }
    __syncthreads();
    if (s_last && wid == 0) {
        float s = 0.0f;
        for (int i = lane; i < NBLK; i += 32) s += d_part[i];
        #pragma unroll
        for (int o = 16; o; o >>= 1)
            s += __shfl_down_sync(0xFFFFFFFFu, s, o);
        if (lane == 0) {
            out[0] = s * (2.0f / (float)(NTOK * 4));  // both L1 terms equal
            d_done = 0;                               // reset for graph replay
            d_cnt  = 0;
        }
    }
}

extern "C" void kernel_launch(void* const* d_in, const int* in_sizes, int n_in,
                              void* d_out, int out_size) {
    const float4* x   = (const float4*)d_in[0];   // [8,4096,4] f32
    const float4* emb = (const float4*)d_in[1];   // [8192,4] f32
    float* out = (float*)d_out;

    vq_stage_kernel<<<NEMB / 256, 256>>>(emb);
    vq_main_kernel<<<NBLK, NTHR>>>(x, emb, out);
}